// round 13
// baseline (speedup 1.0000x reference)
#include <cuda_runtime.h>
#include <math.h>
#include <stdint.h>

#define BB   8
#define SS   128
#define HID  256
#define NH   4
#define DH   64
#define FF   1024
#define MM   (BB*SS)        // 1024 rows
#define PSTR 1280           // proj buffer row stride: q|k|v|aq|ak

// ---------------- scratch ----------------------------------------------------
__device__ float g_P   [MM * PSTR];
__device__ float g_ctx [MM * HID];
__device__ float g_h   [MM * HID];
__device__ float g_ff  [MM * FF];
__device__ float g_part[8 * MM * HID];
__device__ float g_wf  [HID * 512];
__device__ float g_bf  [512];

// ---------------- helpers ------------------------------------------------------
__device__ __forceinline__ void cpa16(uint32_t smem, const void* gmem)
{
    asm volatile("cp.async.cg.shared.global [%0], [%1], 16;" :: "r"(smem), "l"(gmem));
}
#define CP_COMMIT() asm volatile("cp.async.commit_group;" ::: "memory")
#define CP_WAIT0()  asm volatile("cp.async.wait_group 0;" ::: "memory")
#define CP_WAIT1()  asm volatile("cp.async.wait_group 1;" ::: "memory")

__device__ __forceinline__ void mma8(float* d,
                                     uint32_t a0, uint32_t a1, uint32_t a2, uint32_t a3,
                                     uint32_t b0, uint32_t b1)
{
    asm volatile(
        "mma.sync.aligned.m16n8k8.row.col.f32.tf32.tf32.f32 "
        "{%0,%1,%2,%3},{%4,%5,%6,%7},{%8,%9},{%0,%1,%2,%3};"
        : "+f"(d[0]), "+f"(d[1]), "+f"(d[2]), "+f"(d[3])
        : "r"(a0), "r"(a1), "r"(a2), "r"(a3), "r"(b0), "r"(b1));
}

// =============================================================================
// tf32 GEMM body (R11 winner): 128 threads (4 warps), block tile 32x64, BK=16,
// 2-stage cp.async double buffer (wait_group 0 + 1 barrier per K-tile).
// Raw fp32 bits fed to mma.tf32. Warps split 2x2 over (M,N).
// =============================================================================
__device__ __forceinline__ void gemm_tf32(const float* __restrict__ A, int lda,
                                          const float* __restrict__ B, int ldb,
                                          int row0, int col0, int K,
                                          float acc[4][4])
{
    __shared__ uint32_t As[2][32][20];
    __shared__ uint32_t Bs[2][16][68];

    const int tid  = threadIdx.x;
    const int lane = tid & 31;
    const int w    = tid >> 5;
    const int g    = lane >> 2;
    const int tig  = lane & 3;
    const int rb   = (w & 1) << 4;
    const int cb   = (w >> 1) << 5;

    const int ar = tid >> 2, ac = (tid & 3) << 2;
    int br[2], bc[2];
#pragma unroll
    for (int u = 0; u < 2; u++) {
        int f = tid + 128 * u;
        br[u] = f >> 4;  bc[u] = (f & 15) << 2;
    }

    uint32_t sA[2], sB[2][2];
#pragma unroll
    for (int st = 0; st < 2; st++) {
        sA[st] = (uint32_t)__cvta_generic_to_shared(&As[st][ar][ac]);
#pragma unroll
        for (int u = 0; u < 2; u++)
            sB[st][u] = (uint32_t)__cvta_generic_to_shared(&Bs[st][br[u]][bc[u]]);
    }

    const float* Ap = A + (size_t)(row0 + ar) * lda + ac;
    const float* Bp0 = B + (size_t)br[0] * ldb + col0 + bc[0];
    const float* Bp1 = B + (size_t)br[1] * ldb + col0 + bc[1];

#pragma unroll
    for (int t = 0; t < 4; t++)
#pragma unroll
        for (int j = 0; j < 4; j++) acc[t][j] = 0.f;

    // prologue: stage 0
    cpa16(sA[0], Ap);
    cpa16(sB[0][0], Bp0);
    cpa16(sB[0][1], Bp1);
    CP_COMMIT();

    const int nt = K >> 4;
    for (int kt = 0; kt < nt; kt++) {
        const int st = kt & 1;
        CP_WAIT0();
        __syncthreads();

        if (kt + 1 < nt) {
            int k0 = (kt + 1) << 4;
            cpa16(sA[st ^ 1], Ap + k0);
            cpa16(sB[st ^ 1][0], Bp0 + (size_t)k0 * ldb);
            cpa16(sB[st ^ 1][1], Bp1 + (size_t)k0 * ldb);
            CP_COMMIT();
        }

#pragma unroll
        for (int ks = 0; ks < 16; ks += 8) {
            uint32_t a0 = As[st][rb + g][ks + tig];
            uint32_t a1 = As[st][rb + g + 8][ks + tig];
            uint32_t a2 = As[st][rb + g][ks + tig + 4];
            uint32_t a3 = As[st][rb + g + 8][ks + tig + 4];
#pragma unroll
            for (int t = 0; t < 4; t++) {
                uint32_t b0 = Bs[st][ks + tig][cb + t * 8 + g];
                uint32_t b1 = Bs[st][ks + tig + 4][cb + t * 8 + g];
                mma8(acc[t], a0, a1, a2, a3, b0, b1);
            }
        }
    }
}

// =============================================================================
// fusew: wf = [Wq@AWq | Wk@AWk] (fp32 out), bf fused biases. grid (8,9).
// =============================================================================
__global__ __launch_bounds__(128)
void fusew_kernel(const float* __restrict__ Wq, const float* __restrict__ bq,
                  const float* __restrict__ Wk, const float* __restrict__ bk,
                  const float* __restrict__ AWq, const float* __restrict__ Abq,
                  const float* __restrict__ AWk, const float* __restrict__ Abk,
                  float* __restrict__ wf, float* __restrict__ bf)
{
    const int seg = blockIdx.x >> 2;
    const int wcol0 = (blockIdx.x & 3) * 64;

    if (blockIdx.y == 8) {
        const float* bin = seg ? bk : bq;
        const float* AW  = seg ? AWk : AWq;
        const float* Ab  = seg ? Abk : Abq;
        __shared__ float red[128];
        int t = threadIdx.x;
        int c = t & 63, half = t >> 6;
        float s = 0.f;
        for (int d = half * 128; d < half * 128 + 128; d++)
            s += bin[d] * AW[(size_t)d * HID + wcol0 + c];
        red[t] = s;
        __syncthreads();
        if (half == 0)
            bf[seg * 256 + wcol0 + c] = red[c] + red[64 + c] + Ab[wcol0 + c];
        return;
    }

    const float* A = seg ? Wk : Wq;
    const float* B = seg ? AWk : AWq;
    const int row0 = blockIdx.y * 32;
    float acc[4][4];
    gemm_tf32(A, HID, B, HID, row0, wcol0, HID, acc);

    const int lane = threadIdx.x & 31, w = threadIdx.x >> 5;
    const int g = lane >> 2, tig = lane & 3;
    const int rb = (w & 1) << 4, cb = (w >> 1) << 5;
#pragma unroll
    for (int t = 0; t < 4; t++) {
        int c = seg * 256 + wcol0 + cb + t * 8 + tig * 2;
        int r = row0 + rb + g;
        *(float2*)&wf[(size_t)r * 512 + c]       = make_float2(acc[t][0], acc[t][1]);
        *(float2*)&wf[(size_t)(r + 8) * 512 + c] = make_float2(acc[t][2], acc[t][3]);
    }
}

// =============================================================================
// proj: all 5 projections from x. grid (20,32), 128 threads.
// =============================================================================
__global__ __launch_bounds__(128)
void proj_kernel(const float* __restrict__ x,
                 const float* __restrict__ Wq, const float* __restrict__ bq,
                 const float* __restrict__ Wk, const float* __restrict__ bk,
                 const float* __restrict__ Wv, const float* __restrict__ bv,
                 const float* __restrict__ wf, const float* __restrict__ bf,
                 float* __restrict__ P)
{
    const int seg = blockIdx.x >> 2;
    const int wcol0 = (blockIdx.x & 3) * 64;
    const int row0 = blockIdx.y * 32;

    const float* W; const float* bias; int ldb; int bcol;
    if      (seg == 0) { W = Wq; bias = bq;        ldb = HID; bcol = wcol0; }
    else if (seg == 1) { W = Wk; bias = bk;        ldb = HID; bcol = wcol0; }
    else if (seg == 2) { W = Wv; bias = bv;        ldb = HID; bcol = wcol0; }
    else if (seg == 3) { W = wf; bias = bf;        ldb = 512; bcol = wcol0; }
    else               { W = wf; bias = bf + 256;  ldb = 512; bcol = 256 + wcol0; }

    if (seg >= 3) cudaGridDependencySynchronize();

    float acc[4][4];
    gemm_tf32(x, HID, W, ldb, row0, bcol, HID, acc);

    const int lane = threadIdx.x & 31, w = threadIdx.x >> 5;
    const int g = lane >> 2, tig = lane & 3;
    const int rb = (w & 1) << 4, cb = (w >> 1) << 5;
    const int ocol0 = blockIdx.x * 64;
#pragma unroll
    for (int t = 0; t < 4; t++) {
        int c = cb + t * 8 + tig * 2;
        int r = row0 + rb + g;
        float b0 = bias[wcol0 + c], b1 = bias[wcol0 + c + 1];
        *(float2*)&P[(size_t)r * PSTR + ocol0 + c] =
            make_float2(acc[t][0] + b0, acc[t][1] + b1);
        *(float2*)&P[(size_t)(r + 8) * PSTR + ocol0 + c] =
            make_float2(acc[t][2] + b0, acc[t][3] + b1);
    }
}

// =============================================================================
// Split-K partial GEMM. grid (N/64, M/32, NS).
// =============================================================================
template<int NS>
__global__ __launch_bounds__(128)
void gemm_partial_t(const float* __restrict__ A, const float* __restrict__ B,
                    float* __restrict__ Cp, int N, int K)
{
    const int ks = blockIdx.z;
    const int Ks = K / NS;
    const int row0 = blockIdx.y * 32;
    const int col0 = blockIdx.x * 64;

    cudaGridDependencySynchronize();

    float acc[4][4];
    gemm_tf32(A + (size_t)ks * Ks, K, B + (size_t)ks * Ks * N, N, row0, col0, Ks, acc);

    float* C = Cp + (size_t)ks * MM * N;
    const int lane = threadIdx.x & 31, w = threadIdx.x >> 5;
    const int g = lane >> 2, tig = lane & 3;
    const int rb = (w & 1) << 4, cb = (w >> 1) << 5;
#pragma unroll
    for (int t = 0; t < 4; t++) {
        int c = col0 + cb + t * 8 + tig * 2;
        int r = row0 + rb + g;
        *(float2*)&C[(size_t)r * N + c]       = make_float2(acc[t][0], acc[t][1]);
        *(float2*)&C[(size_t)(r + 8) * N + c] = make_float2(acc[t][2], acc[t][3]);
    }
}

// =============================================================================
// W1: h @ W1 + b1, gelu, fp32 out. grid (16,32).
// =============================================================================
__global__ __launch_bounds__(128)
void gemm_w1(const float* __restrict__ A, const float* __restrict__ B,
             const float* __restrict__ bias, float* __restrict__ C)
{
    const int row0 = blockIdx.y * 32;
    const int col0 = blockIdx.x * 64;

    cudaGridDependencySynchronize();

    float acc[4][4];
    gemm_tf32(A, HID, B, FF, row0, col0, HID, acc);

    const int lane = threadIdx.x & 31, w = threadIdx.x >> 5;
    const int g = lane >> 2, tig = lane & 3;
    const int rb = (w & 1) << 4, cb = (w >> 1) << 5;
    const float cg = 0.70710678118654752f;
#pragma unroll
    for (int t = 0; t < 4; t++) {
        int c = col0 + cb + t * 8 + tig * 2;
        int r = row0 + rb + g;
        float b0 = bias[c], b1 = bias[c + 1];
        float v00 = acc[t][0] + b0, v01 = acc[t][1] + b1;
        float v10 = acc[t][2] + b0, v11 = acc[t][3] + b1;
        v00 = 0.5f * v00 * (1.0f + erff(v00 * cg));
        v01 = 0.5f * v01 * (1.0f + erff(v01 * cg));
        v10 = 0.5f * v10 * (1.0f + erff(v10 * cg));
        v11 = 0.5f * v11 * (1.0f + erff(v11 * cg));
        *(float2*)&C[(size_t)r * FF + c]       = make_float2(v00, v01);
        *(float2*)&C[(size_t)(r + 8) * FF + c] = make_float2(v10, v11);
    }
}

// =============================================================================
// Fused attention (R12 pipelined version — kept): 256 threads, 8 warps,
// 2 queries/warp, grid 256 blocks, dynamic smem ~86KB.
// cp.async pipelines k -> (ak | phase1) -> (v | phase2+softmax).
// =============================================================================
#define SM_TILE0  0
#define SM_TILE1  (128*68)
#define SM_QSH    (2*128*68)
#define SM_AQSH   (SM_QSH  + 16*64)
#define SM_PROBS  (SM_AQSH + 16*64)
#define SM_KOKD   (SM_PROBS + 16*128)
#define SM_WSH    (SM_KOKD + 128*2)
#define SM_ATTN_BYTES ((SM_WSH + 256) * 4)

__device__ __forceinline__ void softmax4(const float x[4], float p[4])
{
    float m = fmaxf(fmaxf(x[0], x[1]), fmaxf(x[2], x[3]));
#pragma unroll
    for (int o = 16; o; o >>= 1) m = fmaxf(m, __shfl_xor_sync(0xffffffffu, m, o));
    float e0 = __expf(x[0] - m), e1 = __expf(x[1] - m);
    float e2 = __expf(x[2] - m), e3 = __expf(x[3] - m);
    float s = e0 + e1 + e2 + e3;
#pragma unroll
    for (int o = 16; o; o >>= 1) s += __shfl_xor_sync(0xffffffffu, s, o);
    float r = __fdividef(1.f, s);
    p[0] = e0 * r; p[1] = e1 * r; p[2] = e2 * r; p[3] = e3 * r;
}

__device__ __forceinline__ void softmax_chain(const float s[4], const float as[4],
                                              const float erro[4], const float errd[4],
                                              const float mk[4], float* prow, int lane)
{
    const float inv = 0.125f;
    float rich[4], orig[4], att[4];
#pragma unroll
    for (int jj = 0; jj < 4; jj++) {
        rich[jj] = (s[jj] + erro[jj] + errd[jj]) * inv + mk[jj];
        orig[jj] = s[jj] * inv + mk[jj];
        att[jj]  = as[jj] * inv + mk[jj];
    }
    float rich_p[4], orig_p[4], att_p[4], comb[4], comb_p[4], fin[4], fin_p[4];
    softmax4(rich, rich_p);
    softmax4(orig, orig_p);
    softmax4(att, att_p);
#pragma unroll
    for (int jj = 0; jj < 4; jj++) comb[jj] = orig_p[jj] + 0.5f * rich_p[jj];
    softmax4(comb, comb_p);
#pragma unroll
    for (int jj = 0; jj < 4; jj++) fin[jj] = comb_p[jj] + 0.5f * att_p[jj];
    softmax4(fin, fin_p);
#pragma unroll
    for (int jj = 0; jj < 4; jj++) prow[lane + 32 * jj] = fin_p[jj];
}

__global__ __launch_bounds__(256)
void attn_kernel(const float* __restrict__ P, const float* __restrict__ mask,
                 const float* __restrict__ order_w, const float* __restrict__ order_b,
                 const float* __restrict__ dist_w, const float* __restrict__ dist_b,
                 const float* __restrict__ scalar, float* __restrict__ ctx)
{
    extern __shared__ float sm[];
    float (*tile0)[68] = (float(*)[68])(sm + SM_TILE0);   // k, then v
    float (*tile1)[68] = (float(*)[68])(sm + SM_TILE1);   // ak
    float (*qsh)[64]   = (float(*)[64])(sm + SM_QSH);
    float (*aqsh)[64]  = (float(*)[64])(sm + SM_AQSH);
    float (*probs)[128]= (float(*)[128])(sm + SM_PROBS);
    float (*kokd)[2]   = (float(*)[2])(sm + SM_KOKD);
    float *wsh         = sm + SM_WSH;

    const int tid = threadIdx.x;
    const int lane = tid & 31;
    const int w = tid >> 5;
    const int h = blockIdx.y, b = blockIdx.z;
    const int i0 = blockIdx.x * 16;
    const int ia = i0 + w;
    const int ib = i0 + w + 8;

    const size_t rowbase = ((size_t)b * SS) * PSTR + h * DH;

    // prefetch mask rows + small params (independent inputs) before the sync
    float mkA[4], mkB[4];
#pragma unroll
    for (int jj = 0; jj < 4; jj++) {
        int j = lane + 32 * jj;
        mkA[jj] = mask[((size_t)b * SS + ia) * SS + j];
        mkB[jj] = mask[((size_t)b * SS + ib) * SS + j];
    }
    const float ob = order_b[0], db = dist_b[0], sc = scalar[0];
    wsh[tid] = (tid < 128) ? order_w[tid] : dist_w[tid - 128];

    cudaGridDependencySynchronize();

    // ---- issue k -> tile0 (G0), ak -> tile1 (G1); q/aq via regular LDG
#pragma unroll
    for (int t = 0; t < 8; t++) {
        int f = tid + t * 256;
        int j = f >> 4, d4 = (f & 15) << 2;
        cpa16((uint32_t)__cvta_generic_to_shared(&tile0[j][d4]),
              &P[rowbase + (size_t)j * PSTR + 256 + d4]);
    }
    CP_COMMIT();
#pragma unroll
    for (int t = 0; t < 8; t++) {
        int f = tid + t * 256;
        int j = f >> 4, d4 = (f & 15) << 2;
        cpa16((uint32_t)__cvta_generic_to_shared(&tile1[j][d4]),
              &P[rowbase + (size_t)j * PSTR + 1024 + d4]);
    }
    CP_COMMIT();
    {
        int r = tid >> 4, d4 = (tid & 15) << 2;
        *(float4*)&qsh[r][d4]  = *(const float4*)&P[rowbase + (size_t)(i0 + r) * PSTR + d4];
        *(float4*)&aqsh[r][d4] = *(const float4*)&P[rowbase + (size_t)(i0 + r) * PSTR + 768 + d4];
    }

    CP_WAIT1();         // k tile ready (ak may still be in flight)
    __syncthreads();

    // ---- phase 1: scores q.k + key projections + query projections
    float sA[4] = {0, 0, 0, 0}, sB[4] = {0, 0, 0, 0};
#pragma unroll
    for (int d4 = 0; d4 < 64; d4 += 4) {
        float4 qa = *(const float4*)&qsh[w][d4];
        float4 qb = *(const float4*)&qsh[w + 8][d4];
#pragma unroll
        for (int jj = 0; jj < 4; jj++) {
            float4 kv = *(const float4*)&tile0[lane + 32 * jj][d4];
            sA[jj] = fmaf(qa.x, kv.x, fmaf(qa.y, kv.y, fmaf(qa.z, kv.z, fmaf(qa.w, kv.w, sA[jj]))));
            sB[jj] = fmaf(qb.x, kv.x, fmaf(qb.y, kv.y, fmaf(qb.z, kv.z, fmaf(qb.w, kv.w, sB[jj]))));
        }
    }
    if (tid < 128) {
        float ko = 0, kd = 0;
#pragma unroll
        for (int d4 = 0; d4 < 64; d4 += 4) {
            float4 kv = *(const float4*)&tile0[tid][d4];
            float4 ov = *(const float4*)&wsh[64 + d4];
            float4 dv = *(const float4*)&wsh[192 + d4];
            ko = fmaf(kv.x, ov.x, fmaf(kv.y, ov.y, fmaf(kv.z, ov.z, fmaf(kv.w, ov.w, ko))));
            kd = fmaf(kv.x, dv.x, fmaf(kv.y, dv.y, fmaf(kv.z, dv.z, fmaf(kv.w, dv.w, kd))));
        }
        kokd[tid][0] = ko; kokd[tid][1] = kd;
    }
    float qoA = qsh[w][lane] * wsh[lane] + qsh[w][lane + 32] * wsh[32 + lane];
    float qdA = qsh[w][lane] * wsh[128 + lane] + qsh[w][lane + 32] * wsh[160 + lane];
    float qoB = qsh[w + 8][lane] * wsh[lane] + qsh[w + 8][lane + 32] * wsh[32 + lane];
    float qdB = qsh[w + 8][lane] * wsh[128 + lane] + qsh[w + 8][lane + 32] * wsh[160 + lane];
#pragma unroll
    for (int o = 16; o; o >>= 1) {
        qoA += __shfl_xor_sync(0xffffffffu, qoA, o);
        qdA += __shfl_xor_sync(0xffffffffu, qdA, o);
        qoB += __shfl_xor_sync(0xffffffffu, qoB, o);
        qdB += __shfl_xor_sync(0xffffffffu, qdB, o);
    }
    __syncthreads();    // phase-1 reads of tile0 + wsh(weights) done

    // wsh becomes gdd table; issue v -> tile0 (G2) overlapping phase 2
    wsh[tid] = __logf(fabsf((float)(tid - 128)) + 1.0f);
#pragma unroll
    for (int t = 0; t < 8; t++) {
        int f = tid + t * 256;
        int j = f >> 4, d4 = (f & 15) << 2;
        cpa16((uint32_t)__cvta_generic_to_shared(&tile0[j][d4]),
              &P[rowbase + (size_t)j * PSTR + 512 + d4]);
    }
    CP_COMMIT();

    CP_WAIT1();         // ak tile ready (v may still be in flight)
    __syncthreads();    // gdd visible + ak visible

    // ---- phase 2: attack scores
    float aA[4] = {0, 0, 0, 0}, aB[4] = {0, 0, 0, 0};
#pragma unroll
    for (int d4 = 0; d4 < 64; d4 += 4) {
        float4 qa = *(const float4*)&aqsh[w][d4];
        float4 qb = *(const float4*)&aqsh[w + 8][d4];
#pragma unroll
        for (int jj = 0; jj < 4; jj++) {
            float4 kv = *(const float4*)&tile1[lane + 32 * jj][d4];
            aA[jj] = fmaf(qa.x, kv.x, fmaf(qa.y, kv.y, fmaf(qa.z, kv.z, fmaf(qa.w, kv.w, aA[jj]))));
            aB[jj] = fmaf(qb.x, kv.x, fmaf(qb.y, kv.y, fmaf(qb.z, kv.z, fmaf(qb.w, kv.w, aB[jj]))));
        }
    }

    // ---- error terms + 5 softmaxes per query (v streaming in underneath)
    const float sc2h = 0.5f * sc * sc;
    float erro[4], errd[4];

#pragma unroll
    for (int jj = 0; jj < 4; jj++) {
        int j = lane + 32 * jj;
        float z = qoA + kokd[j][0] + ob;
        float sp = fmaxf(z, 0.f) + __logf(1.f + __expf(-fabsf(z)));
        erro[jj] = ((j > ia) ? z : 0.f) - sp;
        float diff = wsh[j - ia + 128] - (qdA + kokd[j][1] + db);
        errd[jj] = -diff * diff * sc2h;
    }
    softmax_chain(sA, aA, erro, errd, mkA, probs[w], lane);

#pragma unroll
    for (int jj = 0; jj < 4; jj++) {
        int j = lane + 32 * jj;
        float z = qoB + kokd[j][0] + ob;
        float sp = fmaxf(z, 0.f) + __logf(1.f + __expf(-fabsf(z)));
        erro[jj] = ((j > ib) ? z : 0.f) - sp;
        float diff = wsh[j - ib + 128] - (qdB + kokd[j][1] + db);
        errd[jj] = -diff * diff * sc2h;
    }
    softmax_chain(sB, aB, erro, errd, mkB, probs[w + 8], lane);

    CP_WAIT0();         // v tile ready
    __syncthreads();    // probs + v visible

    // ---- context
    float cA0 = 0.f, cA1 = 0.f, cB0 = 0.f, cB1 = 0.f;
#pragma unroll 4
    for (int j = 0; j < 128; j++) {
        float v0 = tile0[j][lane], v1 = tile0[j][lane + 32];
        float pa = probs[w][j], pb = probs[w + 8][j];
        cA0 = fmaf(pa, v0, cA0); cA1 = fmaf(pa, v1, cA1);
        cB0 = fmaf(pb, v0, cB0); cB1 = fmaf(pb, v1, cB1);
    }
    size_t oA = ((size_t)(b * SS + ia)) * HID + h * DH;
    size_t oB = ((size_t)(b * SS + ib)) * HID + h * DH;
    ctx[oA + lane]      = cA0;
    ctx[oA + lane + 32] = cA1;
    ctx[oB + lane]      = cB0;
    ctx[oB + lane + 32] = cB1;
}

// =============================================================================
// LayerNorm over NP split-K partials + bias + residual.
// =============================================================================
template<int NP>
__global__ __launch_bounds__(256)
void ln_kernel(const float* __restrict__ Cp, const float* __restrict__ bias,
               const float* __restrict__ res, const float* __restrict__ g,
               const float* __restrict__ beta, float* __restrict__ out,
               int res_dep)
{
    int row = blockIdx.x;
    int t = threadIdx.x;
    int lane = t & 31, w = t >> 5;
    __shared__ float red[8];

    const size_t SZ = (size_t)MM * HID;
    size_t idx = (size_t)row * HID + t;

    float x;
    if (res_dep) {
        cudaGridDependencySynchronize();
        x = bias[t] + res[idx];
    } else {
        x = bias[t] + res[idx];
        cudaGridDependencySynchronize();
    }
#pragma unroll
    for (int p = 0; p < NP; p++) x += Cp[p * SZ + idx];

    float v = x;
#pragma unroll
    for (int o = 16; o; o >>= 1) v += __shfl_xor_sync(0xffffffffu, v, o);
    if (lane == 0) red[w] = v;
    __syncthreads();
    float mean;
    {
        float r = (lane < 8) ? red[lane] : 0.f;
#pragma unroll
        for (int o = 4; o; o >>= 1) r += __shfl_xor_sync(0xffffffffu, r, o);
        mean = __shfl_sync(0xffffffffu, r, 0) * (1.0f / HID);
    }
    float d = x - mean;
    v = d * d;
#pragma unroll
    for (int o = 16; o; o >>= 1) v += __shfl_xor_sync(0xffffffffu, v, o);
    __syncthreads();
    if (lane == 0) red[w] = v;
    __syncthreads();
    float var;
    {
        float r = (lane < 8) ? red[lane] : 0.f;
#pragma unroll
        for (int o = 4; o; o >>= 1) r += __shfl_xor_sync(0xffffffffu, r, o);
        var = __shfl_sync(0xffffffffu, r, 0) * (1.0f / HID);
    }
    float invs = rsqrtf(var + 1e-12f);
    out[idx] = d * invs * g[t] + beta[t];
}

// ---------------- PDL launcher -------------------------------------------------
static inline void launch_pdl(const void* func, dim3 grid, dim3 block, void** args,
                              size_t dsmem = 0)
{
    cudaLaunchConfig_t cfg = {};
    cfg.gridDim = grid;
    cfg.blockDim = block;
    cfg.dynamicSmemBytes = dsmem;
    cfg.stream = 0;
    cudaLaunchAttribute attr[1];
    attr[0].id = cudaLaunchAttributeProgrammaticStreamSerialization;
    attr[0].val.programmaticStreamSerializationAllowed = 1;
    cfg.attrs = attr;
    cfg.numAttrs = 1;
    cudaLaunchKernelExC(&cfg, func, args);
}

// ---------------- launch -----------------------------------------------------
extern "C" void kernel_launch(void* const* d_in, const int* in_sizes, int n_in,
                              void* d_out, int out_size)
{
    const float* x       = (const float*)d_in[0];
    const float* mask    = (const float*)d_in[1];
    const float* Wq      = (const float*)d_in[2];
    const float* bq      = (const float*)d_in[3];
    const float* Wk      = (const float*)d_in[4];
    const float* bk      = (const float*)d_in[5];
    const float* Wv      = (const float*)d_in[6];
    const float* bv      = (const float*)d_in[7];
    const float* order_w = (const float*)d_in[8];
    const float* order_b = (const float*)d_in[9];
    const float* dist_w  = (const float*)d_in[10];
    const float* dist_b  = (const float*)d_in[11];
    const float* scalar  = (const float*)d_in[12];
    const float* AWq     = (const float*)d_in[13];
    const float* Abq     = (const float*)d_in[14];
    const float* AWk     = (const float*)d_in[15];
    const float* Abk     = (const float*)d_in[16];
    const float* Wd      = (const float*)d_in[17];
    const float* bd      = (const float*)d_in[18];
    const float* g1      = (const float*)d_in[19];
    const float* beta1   = (const float*)d_in[20];
    const float* W1      = (const float*)d_in[21];
    const float* b1      = (const float*)d_in[22];
    const float* W2      = (const float*)d_in[23];
    const float* b2      = (const float*)d_in[24];
    const float* g2      = (const float*)d_in[25];
    const float* beta2   = (const float*)d_in[26];
    float* out = (float*)d_out;

    float *P, *ctx, *hbuf, *ffb, *part, *wf, *bf;
    cudaGetSymbolAddress((void**)&P,    g_P);
    cudaGetSymbolAddress((void**)&ctx,  g_ctx);
    cudaGetSymbolAddress((void**)&hbuf, g_h);
    cudaGetSymbolAddress((void**)&ffb,  g_ff);
    cudaGetSymbolAddress((void**)&part, g_part);
    cudaGetSymbolAddress((void**)&wf,   g_wf);
    cudaGetSymbolAddress((void**)&bf,   g_bf);

    // allow large dynamic smem for attn (idempotent; not a graph op)
    cudaFuncSetAttribute((const void*)attn_kernel,
                         cudaFuncAttributeMaxDynamicSharedMemorySize, SM_ATTN_BYTES);

    // 1) fused attack weights + biases (plain launch; head of chain)
    fusew_kernel<<<dim3(8, 9), 128>>>(Wq, bq, Wk, bk, AWq, Abq, AWk, Abk, wf, bf);

    // 2) all 5 projections — PDL (segs 0-2 overlap fusew)
    {
        void* a[] = {&x, &Wq, &bq, &Wk, &bk, &Wv, &bv, &wf, &bf, &P};
        launch_pdl((const void*)proj_kernel, dim3(20, 32), dim3(128), a);
    }

    // 3) fused attention — PDL, dynamic smem
    {
        void* a[] = {&P, &mask, &order_w, &order_b, &dist_w, &dist_b, &scalar, &ctx};
        launch_pdl((const void*)attn_kernel, dim3(SS / 16, NH, BB), dim3(256), a,
                   SM_ATTN_BYTES);
    }

    // 4) Wd split-K=8 (1024 blocks) — PDL
    {
        int N = HID, K = HID;
        void* a[] = {&ctx, &Wd, &part, &N, &K};
        launch_pdl((const void*)gemm_partial_t<8>, dim3(4, 32, 8), dim3(128), a);
    }

    // 5) LN1 — PDL
    {
        int dep = 0;
        void* a[] = {&part, &bd, &x, &g1, &beta1, &hbuf, &dep};
        launch_pdl((const void*)ln_kernel<8>, dim3(MM), dim3(256), a);
    }

    // 6) W1 + gelu — PDL
    {
        void* a[] = {&hbuf, &W1, &b1, &ffb};
        launch_pdl((const void*)gemm_w1, dim3(16, 32), dim3(128), a);
    }

    // 7) W2 split-K=8 — PDL
    {
        int N = HID, K = FF;
        void* a[] = {&ffb, &W2, &part, &N, &K};
        launch_pdl((const void*)gemm_partial_t<8>, dim3(4, 32, 8), dim3(128), a);
    }

    // 8) LN2 — PDL
    {
        int dep = 1;
        void* a[] = {&part, &b2, &hbuf, &g2, &beta2, &out, &dep};
        launch_pdl((const void*)ln_kernel<8>, dim3(MM), dim3(256), a);
    }
}

// round 14
// speedup vs baseline: 1.0185x; 1.0185x over previous
#include <cuda_runtime.h>
#include <math.h>
#include <stdint.h>

#define BB   8
#define SS   128
#define HID  256
#define NH   4
#define DH   64
#define FF   1024
#define MM   (BB*SS)        // 1024 rows
#define PSTR 1280           // proj buffer row stride: q|k|v|aq|ak

// ---------------- scratch ----------------------------------------------------
__device__ float g_P   [MM * PSTR];
__device__ float g_ctx [MM * HID];
__device__ float g_h   [MM * HID];
__device__ float g_ff  [MM * FF];
__device__ float g_part[8 * MM * HID];
__device__ float g_wf  [HID * 512];
__device__ float g_bf  [512];

// ---------------- helpers ------------------------------------------------------
__device__ __forceinline__ void cpa16(uint32_t smem, const void* gmem)
{
    asm volatile("cp.async.cg.shared.global [%0], [%1], 16;" :: "r"(smem), "l"(gmem));
}
#define CP_COMMIT() asm volatile("cp.async.commit_group;" ::: "memory")
#define CP_WAIT0()  asm volatile("cp.async.wait_group 0;" ::: "memory")

__device__ __forceinline__ void mma8(float* d,
                                     uint32_t a0, uint32_t a1, uint32_t a2, uint32_t a3,
                                     uint32_t b0, uint32_t b1)
{
    asm volatile(
        "mma.sync.aligned.m16n8k8.row.col.f32.tf32.tf32.f32 "
        "{%0,%1,%2,%3},{%4,%5,%6,%7},{%8,%9},{%0,%1,%2,%3};"
        : "+f"(d[0]), "+f"(d[1]), "+f"(d[2]), "+f"(d[3])
        : "r"(a0), "r"(a1), "r"(a2), "r"(a3), "r"(b0), "r"(b1));
}

// =============================================================================
// tf32 GEMM body: 128 threads (4 warps), block tile 32x64, BK=32,
// 2-stage cp.async double buffer (1 wait + 1 barrier per 32-deep K-tile,
// 32 MMAs between barriers). Raw fp32 bits fed to mma.tf32.
// Warps split 2x2 over (M,N): warp computes 16 rows x 32 cols.
// =============================================================================
__device__ __forceinline__ void gemm_tf32(const float* __restrict__ A, int lda,
                                          const float* __restrict__ B, int ldb,
                                          int row0, int col0, int K,
                                          float acc[4][4])
{
    __shared__ uint32_t As[2][32][36];   // [m][k], pad 36 (144B rows, 16B aligned)
    __shared__ uint32_t Bs[2][32][68];   // [k][n], pad 68 (272B rows, 16B aligned)

    const int tid  = threadIdx.x;
    const int lane = tid & 31;
    const int w    = tid >> 5;
    const int g    = lane >> 2;
    const int tig  = lane & 3;
    const int rb   = (w & 1) << 4;
    const int cb   = (w >> 1) << 5;

    // A: 32x32 = 256 uint4 (2/thread); B: 32x64 = 512 uint4 (4/thread)
    int ar[2], ac[2], br[4], bc[4];
#pragma unroll
    for (int u = 0; u < 2; u++) {
        int f = tid + 128 * u;
        ar[u] = f >> 3;  ac[u] = (f & 7) << 2;
    }
#pragma unroll
    for (int u = 0; u < 4; u++) {
        int f = tid + 128 * u;
        br[u] = f >> 4;  bc[u] = (f & 15) << 2;
    }

    uint32_t sA[2][2], sB[2][4];
#pragma unroll
    for (int st = 0; st < 2; st++) {
#pragma unroll
        for (int u = 0; u < 2; u++)
            sA[st][u] = (uint32_t)__cvta_generic_to_shared(&As[st][ar[u]][ac[u]]);
#pragma unroll
        for (int u = 0; u < 4; u++)
            sB[st][u] = (uint32_t)__cvta_generic_to_shared(&Bs[st][br[u]][bc[u]]);
    }

    const float* Ap[2];
    const float* Bp[4];
#pragma unroll
    for (int u = 0; u < 2; u++) Ap[u] = A + (size_t)(row0 + ar[u]) * lda + ac[u];
#pragma unroll
    for (int u = 0; u < 4; u++) Bp[u] = B + (size_t)br[u] * ldb + col0 + bc[u];

#pragma unroll
    for (int t = 0; t < 4; t++)
#pragma unroll
        for (int j = 0; j < 4; j++) acc[t][j] = 0.f;

    // prologue: stage 0
#pragma unroll
    for (int u = 0; u < 2; u++) cpa16(sA[0][u], Ap[u]);
#pragma unroll
    for (int u = 0; u < 4; u++) cpa16(sB[0][u], Bp[u]);
    CP_COMMIT();

    const int nt = K >> 5;
    for (int kt = 0; kt < nt; kt++) {
        const int st = kt & 1;
        CP_WAIT0();
        __syncthreads();

        if (kt + 1 < nt) {
            int k0 = (kt + 1) << 5;
#pragma unroll
            for (int u = 0; u < 2; u++) cpa16(sA[st ^ 1][u], Ap[u] + k0);
#pragma unroll
            for (int u = 0; u < 4; u++) cpa16(sB[st ^ 1][u], Bp[u] + (size_t)k0 * ldb);
            CP_COMMIT();
        }

#pragma unroll
        for (int ks = 0; ks < 32; ks += 8) {
            uint32_t a0 = As[st][rb + g][ks + tig];
            uint32_t a1 = As[st][rb + g + 8][ks + tig];
            uint32_t a2 = As[st][rb + g][ks + tig + 4];
            uint32_t a3 = As[st][rb + g + 8][ks + tig + 4];
#pragma unroll
            for (int t = 0; t < 4; t++) {
                uint32_t b0 = Bs[st][ks + tig][cb + t * 8 + g];
                uint32_t b1 = Bs[st][ks + tig + 4][cb + t * 8 + g];
                mma8(acc[t], a0, a1, a2, a3, b0, b1);
            }
        }
    }
}

// =============================================================================
// fusew: wf = [Wq@AWq | Wk@AWk] (fp32 out), bf fused biases. grid (8,9).
// =============================================================================
__global__ __launch_bounds__(128)
void fusew_kernel(const float* __restrict__ Wq, const float* __restrict__ bq,
                  const float* __restrict__ Wk, const float* __restrict__ bk,
                  const float* __restrict__ AWq, const float* __restrict__ Abq,
                  const float* __restrict__ AWk, const float* __restrict__ Abk,
                  float* __restrict__ wf, float* __restrict__ bf)
{
    const int seg = blockIdx.x >> 2;
    const int wcol0 = (blockIdx.x & 3) * 64;

    if (blockIdx.y == 8) {
        const float* bin = seg ? bk : bq;
        const float* AW  = seg ? AWk : AWq;
        const float* Ab  = seg ? Abk : Abq;
        __shared__ float red[128];
        int t = threadIdx.x;
        int c = t & 63, half = t >> 6;
        float s = 0.f;
        for (int d = half * 128; d < half * 128 + 128; d++)
            s += bin[d] * AW[(size_t)d * HID + wcol0 + c];
        red[t] = s;
        __syncthreads();
        if (half == 0)
            bf[seg * 256 + wcol0 + c] = red[c] + red[64 + c] + Ab[wcol0 + c];
        return;
    }

    const float* A = seg ? Wk : Wq;
    const float* B = seg ? AWk : AWq;
    const int row0 = blockIdx.y * 32;
    float acc[4][4];
    gemm_tf32(A, HID, B, HID, row0, wcol0, HID, acc);

    const int lane = threadIdx.x & 31, w = threadIdx.x >> 5;
    const int g = lane >> 2, tig = lane & 3;
    const int rb = (w & 1) << 4, cb = (w >> 1) << 5;
#pragma unroll
    for (int t = 0; t < 4; t++) {
        int c = seg * 256 + wcol0 + cb + t * 8 + tig * 2;
        int r = row0 + rb + g;
        *(float2*)&wf[(size_t)r * 512 + c]       = make_float2(acc[t][0], acc[t][1]);
        *(float2*)&wf[(size_t)(r + 8) * 512 + c] = make_float2(acc[t][2], acc[t][3]);
    }
}

// =============================================================================
// proj: all 5 projections from x. grid (20,32), 128 threads.
// =============================================================================
__global__ __launch_bounds__(128)
void proj_kernel(const float* __restrict__ x,
                 const float* __restrict__ Wq, const float* __restrict__ bq,
                 const float* __restrict__ Wk, const float* __restrict__ bk,
                 const float* __restrict__ Wv, const float* __restrict__ bv,
                 const float* __restrict__ wf, const float* __restrict__ bf,
                 float* __restrict__ P)
{
    const int seg = blockIdx.x >> 2;
    const int wcol0 = (blockIdx.x & 3) * 64;
    const int row0 = blockIdx.y * 32;

    const float* W; const float* bias; int ldb; int bcol;
    if      (seg == 0) { W = Wq; bias = bq;        ldb = HID; bcol = wcol0; }
    else if (seg == 1) { W = Wk; bias = bk;        ldb = HID; bcol = wcol0; }
    else if (seg == 2) { W = Wv; bias = bv;        ldb = HID; bcol = wcol0; }
    else if (seg == 3) { W = wf; bias = bf;        ldb = 512; bcol = wcol0; }
    else               { W = wf; bias = bf + 256;  ldb = 512; bcol = 256 + wcol0; }

    if (seg >= 3) cudaGridDependencySynchronize();

    float acc[4][4];
    gemm_tf32(x, HID, W, ldb, row0, bcol, HID, acc);

    const int lane = threadIdx.x & 31, w = threadIdx.x >> 5;
    const int g = lane >> 2, tig = lane & 3;
    const int rb = (w & 1) << 4, cb = (w >> 1) << 5;
    const int ocol0 = blockIdx.x * 64;
#pragma unroll
    for (int t = 0; t < 4; t++) {
        int c = cb + t * 8 + tig * 2;
        int r = row0 + rb + g;
        float b0 = bias[wcol0 + c], b1 = bias[wcol0 + c + 1];
        *(float2*)&P[(size_t)r * PSTR + ocol0 + c] =
            make_float2(acc[t][0] + b0, acc[t][1] + b1);
        *(float2*)&P[(size_t)(r + 8) * PSTR + ocol0 + c] =
            make_float2(acc[t][2] + b0, acc[t][3] + b1);
    }
}

// =============================================================================
// Split-K partial GEMM. grid (N/64, M/32, NS).
// =============================================================================
template<int NS>
__global__ __launch_bounds__(128)
void gemm_partial_t(const float* __restrict__ A, const float* __restrict__ B,
                    float* __restrict__ Cp, int N, int K)
{
    const int ks = blockIdx.z;
    const int Ks = K / NS;
    const int row0 = blockIdx.y * 32;
    const int col0 = blockIdx.x * 64;

    cudaGridDependencySynchronize();

    float acc[4][4];
    gemm_tf32(A + (size_t)ks * Ks, K, B + (size_t)ks * Ks * N, N, row0, col0, Ks, acc);

    float* C = Cp + (size_t)ks * MM * N;
    const int lane = threadIdx.x & 31, w = threadIdx.x >> 5;
    const int g = lane >> 2, tig = lane & 3;
    const int rb = (w & 1) << 4, cb = (w >> 1) << 5;
#pragma unroll
    for (int t = 0; t < 4; t++) {
        int c = col0 + cb + t * 8 + tig * 2;
        int r = row0 + rb + g;
        *(float2*)&C[(size_t)r * N + c]       = make_float2(acc[t][0], acc[t][1]);
        *(float2*)&C[(size_t)(r + 8) * N + c] = make_float2(acc[t][2], acc[t][3]);
    }
}

// =============================================================================
// W1: h @ W1 + b1, gelu, fp32 out. grid (16,32).
// =============================================================================
__global__ __launch_bounds__(128)
void gemm_w1(const float* __restrict__ A, const float* __restrict__ B,
             const float* __restrict__ bias, float* __restrict__ C)
{
    const int row0 = blockIdx.y * 32;
    const int col0 = blockIdx.x * 64;

    cudaGridDependencySynchronize();

    float acc[4][4];
    gemm_tf32(A, HID, B, FF, row0, col0, HID, acc);

    const int lane = threadIdx.x & 31, w = threadIdx.x >> 5;
    const int g = lane >> 2, tig = lane & 3;
    const int rb = (w & 1) << 4, cb = (w >> 1) << 5;
    const float cg = 0.70710678118654752f;
#pragma unroll
    for (int t = 0; t < 4; t++) {
        int c = col0 + cb + t * 8 + tig * 2;
        int r = row0 + rb + g;
        float b0 = bias[c], b1 = bias[c + 1];
        float v00 = acc[t][0] + b0, v01 = acc[t][1] + b1;
        float v10 = acc[t][2] + b0, v11 = acc[t][3] + b1;
        v00 = 0.5f * v00 * (1.0f + erff(v00 * cg));
        v01 = 0.5f * v01 * (1.0f + erff(v01 * cg));
        v10 = 0.5f * v10 * (1.0f + erff(v10 * cg));
        v11 = 0.5f * v11 * (1.0f + erff(v11 * cg));
        *(float2*)&C[(size_t)r * FF + c]       = make_float2(v00, v01);
        *(float2*)&C[(size_t)(r + 8) * FF + c] = make_float2(v10, v11);
    }
}

// =============================================================================
// Fused attention (R11 winner): 256 threads, 8 warps, 2 queries/warp,
// static 48KB smem, grid 256 blocks. Mask prefetch before PDL sync.
// =============================================================================
__device__ __forceinline__ void softmax4(const float x[4], float p[4])
{
    float m = fmaxf(fmaxf(x[0], x[1]), fmaxf(x[2], x[3]));
#pragma unroll
    for (int o = 16; o; o >>= 1) m = fmaxf(m, __shfl_xor_sync(0xffffffffu, m, o));
    float e0 = __expf(x[0] - m), e1 = __expf(x[1] - m);
    float e2 = __expf(x[2] - m), e3 = __expf(x[3] - m);
    float s = e0 + e1 + e2 + e3;
#pragma unroll
    for (int o = 16; o; o >>= 1) s += __shfl_xor_sync(0xffffffffu, s, o);
    float r = __fdividef(1.f, s);
    p[0] = e0 * r; p[1] = e1 * r; p[2] = e2 * r; p[3] = e3 * r;
}

__device__ __forceinline__ void softmax_chain(const float s[4], const float as[4],
                                              const float erro[4], const float errd[4],
                                              const float mk[4], float* prow, int lane)
{
    const float inv = 0.125f;
    float rich[4], orig[4], att[4];
#pragma unroll
    for (int jj = 0; jj < 4; jj++) {
        rich[jj] = (s[jj] + erro[jj] + errd[jj]) * inv + mk[jj];
        orig[jj] = s[jj] * inv + mk[jj];
        att[jj]  = as[jj] * inv + mk[jj];
    }
    float rich_p[4], orig_p[4], att_p[4], comb[4], comb_p[4], fin[4], fin_p[4];
    softmax4(rich, rich_p);
    softmax4(orig, orig_p);
    softmax4(att, att_p);
#pragma unroll
    for (int jj = 0; jj < 4; jj++) comb[jj] = orig_p[jj] + 0.5f * rich_p[jj];
    softmax4(comb, comb_p);
#pragma unroll
    for (int jj = 0; jj < 4; jj++) fin[jj] = comb_p[jj] + 0.5f * att_p[jj];
    softmax4(fin, fin_p);
#pragma unroll
    for (int jj = 0; jj < 4; jj++) prow[lane + 32 * jj] = fin_p[jj];
}

__global__ __launch_bounds__(256)
void attn_kernel(const float* __restrict__ P, const float* __restrict__ mask,
                 const float* __restrict__ order_w, const float* __restrict__ order_b,
                 const float* __restrict__ dist_w, const float* __restrict__ dist_b,
                 const float* __restrict__ scalar, float* __restrict__ ctx)
{
    __shared__ float tile[128][68];     // k -> ak -> v
    __shared__ float qsh[16][64];       // q -> aq
    __shared__ float probs[16][128];
    __shared__ float kokd[128][2];
    __shared__ float wsh[256];          // order_w|dist_w, later gdd table

    const int tid = threadIdx.x;
    const int lane = tid & 31;
    const int w = tid >> 5;
    const int h = blockIdx.y, b = blockIdx.z;
    const int i0 = blockIdx.x * 16;
    const int ia = i0 + w;
    const int ib = i0 + w + 8;

    const size_t rowbase = ((size_t)b * SS) * PSTR + h * DH;

    // prefetch mask rows + small params (independent inputs) before the sync
    float mkA[4], mkB[4];
#pragma unroll
    for (int jj = 0; jj < 4; jj++) {
        int j = lane + 32 * jj;
        mkA[jj] = mask[((size_t)b * SS + ia) * SS + j];
        mkB[jj] = mask[((size_t)b * SS + ib) * SS + j];
    }
    const float ob = order_b[0], db = dist_b[0], sc = scalar[0];
    wsh[tid] = (tid < 128) ? order_w[tid] : dist_w[tid - 128];

    cudaGridDependencySynchronize();

    // ---- phase 1: k tile + q rows
#pragma unroll
    for (int f = tid; f < 128 * 16; f += 256) {
        int j = f >> 4, d4 = (f & 15) << 2;
        *(float4*)&tile[j][d4] = *(const float4*)&P[rowbase + (size_t)j * PSTR + 256 + d4];
    }
    {
        int r = tid >> 4, d4 = (tid & 15) << 2;
        *(float4*)&qsh[r][d4] = *(const float4*)&P[rowbase + (size_t)(i0 + r) * PSTR + d4];
    }
    __syncthreads();

    float sA[4] = {0, 0, 0, 0}, sB[4] = {0, 0, 0, 0};
#pragma unroll
    for (int d4 = 0; d4 < 64; d4 += 4) {
        float4 qa = *(const float4*)&qsh[w][d4];
        float4 qb = *(const float4*)&qsh[w + 8][d4];
#pragma unroll
        for (int jj = 0; jj < 4; jj++) {
            float4 kv = *(const float4*)&tile[lane + 32 * jj][d4];
            sA[jj] = fmaf(qa.x, kv.x, fmaf(qa.y, kv.y, fmaf(qa.z, kv.z, fmaf(qa.w, kv.w, sA[jj]))));
            sB[jj] = fmaf(qb.x, kv.x, fmaf(qb.y, kv.y, fmaf(qb.z, kv.z, fmaf(qb.w, kv.w, sB[jj]))));
        }
    }
    if (tid < 128) {
        float ko = 0, kd = 0;
#pragma unroll
        for (int d4 = 0; d4 < 64; d4 += 4) {
            float4 kv = *(const float4*)&tile[tid][d4];
            float4 ov = *(const float4*)&wsh[64 + d4];
            float4 dv = *(const float4*)&wsh[192 + d4];
            ko = fmaf(kv.x, ov.x, fmaf(kv.y, ov.y, fmaf(kv.z, ov.z, fmaf(kv.w, ov.w, ko))));
            kd = fmaf(kv.x, dv.x, fmaf(kv.y, dv.y, fmaf(kv.z, dv.z, fmaf(kv.w, dv.w, kd))));
        }
        kokd[tid][0] = ko; kokd[tid][1] = kd;
    }
    float qoA = qsh[w][lane] * wsh[lane] + qsh[w][lane + 32] * wsh[32 + lane];
    float qdA = qsh[w][lane] * wsh[128 + lane] + qsh[w][lane + 32] * wsh[160 + lane];
    float qoB = qsh[w + 8][lane] * wsh[lane] + qsh[w + 8][lane + 32] * wsh[32 + lane];
    float qdB = qsh[w + 8][lane] * wsh[128 + lane] + qsh[w + 8][lane + 32] * wsh[160 + lane];
#pragma unroll
    for (int o = 16; o; o >>= 1) {
        qoA += __shfl_xor_sync(0xffffffffu, qoA, o);
        qdA += __shfl_xor_sync(0xffffffffu, qdA, o);
        qoB += __shfl_xor_sync(0xffffffffu, qoB, o);
        qdB += __shfl_xor_sync(0xffffffffu, qdB, o);
    }
    __syncthreads();

    // ---- phase 2: ak tile + aq rows; wsh becomes gdd table
#pragma unroll
    for (int f = tid; f < 128 * 16; f += 256) {
        int j = f >> 4, d4 = (f & 15) << 2;
        *(float4*)&tile[j][d4] = *(const float4*)&P[rowbase + (size_t)j * PSTR + 1024 + d4];
    }
    {
        int r = tid >> 4, d4 = (tid & 15) << 2;
        *(float4*)&qsh[r][d4] = *(const float4*)&P[rowbase + (size_t)(i0 + r) * PSTR + 768 + d4];
    }
    wsh[tid] = __logf(fabsf((float)(tid - 128)) + 1.0f);
    __syncthreads();

    float aA[4] = {0, 0, 0, 0}, aB[4] = {0, 0, 0, 0};
#pragma unroll
    for (int d4 = 0; d4 < 64; d4 += 4) {
        float4 qa = *(const float4*)&qsh[w][d4];
        float4 qb = *(const float4*)&qsh[w + 8][d4];
#pragma unroll
        for (int jj = 0; jj < 4; jj++) {
            float4 kv = *(const float4*)&tile[lane + 32 * jj][d4];
            aA[jj] = fmaf(qa.x, kv.x, fmaf(qa.y, kv.y, fmaf(qa.z, kv.z, fmaf(qa.w, kv.w, aA[jj]))));
            aB[jj] = fmaf(qb.x, kv.x, fmaf(qb.y, kv.y, fmaf(qb.z, kv.z, fmaf(qb.w, kv.w, aB[jj]))));
        }
    }
    __syncthreads();   // ak reads done; tile free for v

    // issue v loads (overlap with softmax math)
    float4 vreg[8];
#pragma unroll
    for (int t = 0; t < 8; t++) {
        int f = tid + t * 256;
        int j = f >> 4, d4 = (f & 15) << 2;
        vreg[t] = *(const float4*)&P[rowbase + (size_t)j * PSTR + 512 + d4];
    }

    const float sc2h = 0.5f * sc * sc;
    float erro[4], errd[4];

    // query A
#pragma unroll
    for (int jj = 0; jj < 4; jj++) {
        int j = lane + 32 * jj;
        float z = qoA + kokd[j][0] + ob;
        float sp = fmaxf(z, 0.f) + __logf(1.f + __expf(-fabsf(z)));
        erro[jj] = ((j > ia) ? z : 0.f) - sp;
        float diff = wsh[j - ia + 128] - (qdA + kokd[j][1] + db);
        errd[jj] = -diff * diff * sc2h;
    }
    softmax_chain(sA, aA, erro, errd, mkA, probs[w], lane);

    // query B
#pragma unroll
    for (int jj = 0; jj < 4; jj++) {
        int j = lane + 32 * jj;
        float z = qoB + kokd[j][0] + ob;
        float sp = fmaxf(z, 0.f) + __logf(1.f + __expf(-fabsf(z)));
        erro[jj] = ((j > ib) ? z : 0.f) - sp;
        float diff = wsh[j - ib + 128] - (qdB + kokd[j][1] + db);
        errd[jj] = -diff * diff * sc2h;
    }
    softmax_chain(sB, aB, erro, errd, mkB, probs[w + 8], lane);

    // commit v tile
#pragma unroll
    for (int t = 0; t < 8; t++) {
        int f = tid + t * 256;
        int j = f >> 4, d4 = (f & 15) << 2;
        *(float4*)&tile[j][d4] = vreg[t];
    }
    __syncthreads();

    float cA0 = 0.f, cA1 = 0.f, cB0 = 0.f, cB1 = 0.f;
#pragma unroll 4
    for (int j = 0; j < 128; j++) {
        float v0 = tile[j][lane], v1 = tile[j][lane + 32];
        float pa = probs[w][j], pb = probs[w + 8][j];
        cA0 = fmaf(pa, v0, cA0); cA1 = fmaf(pa, v1, cA1);
        cB0 = fmaf(pb, v0, cB0); cB1 = fmaf(pb, v1, cB1);
    }
    size_t oA = ((size_t)(b * SS + ia)) * HID + h * DH;
    size_t oB = ((size_t)(b * SS + ib)) * HID + h * DH;
    ctx[oA + lane]      = cA0;
    ctx[oA + lane + 32] = cA1;
    ctx[oB + lane]      = cB0;
    ctx[oB + lane + 32] = cB1;
}

// =============================================================================
// LayerNorm over NP split-K partials + bias + residual.
// =============================================================================
template<int NP>
__global__ __launch_bounds__(256)
void ln_kernel(const float* __restrict__ Cp, const float* __restrict__ bias,
               const float* __restrict__ res, const float* __restrict__ g,
               const float* __restrict__ beta, float* __restrict__ out,
               int res_dep)
{
    int row = blockIdx.x;
    int t = threadIdx.x;
    int lane = t & 31, w = t >> 5;
    __shared__ float red[8];

    const size_t SZ = (size_t)MM * HID;
    size_t idx = (size_t)row * HID + t;

    float x;
    if (res_dep) {
        cudaGridDependencySynchronize();
        x = bias[t] + res[idx];
    } else {
        x = bias[t] + res[idx];
        cudaGridDependencySynchronize();
    }
#pragma unroll
    for (int p = 0; p < NP; p++) x += Cp[p * SZ + idx];

    float v = x;
#pragma unroll
    for (int o = 16; o; o >>= 1) v += __shfl_xor_sync(0xffffffffu, v, o);
    if (lane == 0) red[w] = v;
    __syncthreads();
    float mean;
    {
        float r = (lane < 8) ? red[lane] : 0.f;
#pragma unroll
        for (int o = 4; o; o >>= 1) r += __shfl_xor_sync(0xffffffffu, r, o);
        mean = __shfl_sync(0xffffffffu, r, 0) * (1.0f / HID);
    }
    float d = x - mean;
    v = d * d;
#pragma unroll
    for (int o = 16; o; o >>= 1) v += __shfl_xor_sync(0xffffffffu, v, o);
    __syncthreads();
    if (lane == 0) red[w] = v;
    __syncthreads();
    float var;
    {
        float r = (lane < 8) ? red[lane] : 0.f;
#pragma unroll
        for (int o = 4; o; o >>= 1) r += __shfl_xor_sync(0xffffffffu, r, o);
        var = __shfl_sync(0xffffffffu, r, 0) * (1.0f / HID);
    }
    float invs = rsqrtf(var + 1e-12f);
    out[idx] = d * invs * g[t] + beta[t];
}

// ---------------- PDL launcher -------------------------------------------------
static inline void launch_pdl(const void* func, dim3 grid, dim3 block, void** args)
{
    cudaLaunchConfig_t cfg = {};
    cfg.gridDim = grid;
    cfg.blockDim = block;
    cfg.dynamicSmemBytes = 0;
    cfg.stream = 0;
    cudaLaunchAttribute attr[1];
    attr[0].id = cudaLaunchAttributeProgrammaticStreamSerialization;
    attr[0].val.programmaticStreamSerializationAllowed = 1;
    cfg.attrs = attr;
    cfg.numAttrs = 1;
    cudaLaunchKernelExC(&cfg, func, args);
}

// ---------------- launch -----------------------------------------------------
extern "C" void kernel_launch(void* const* d_in, const int* in_sizes, int n_in,
                              void* d_out, int out_size)
{
    const float* x       = (const float*)d_in[0];
    const float* mask    = (const float*)d_in[1];
    const float* Wq      = (const float*)d_in[2];
    const float* bq      = (const float*)d_in[3];
    const float* Wk      = (const float*)d_in[4];
    const float* bk      = (const float*)d_in[5];
    const float* Wv      = (const float*)d_in[6];
    const float* bv      = (const float*)d_in[7];
    const float* order_w = (const float*)d_in[8];
    const float* order_b = (const float*)d_in[9];
    const float* dist_w  = (const float*)d_in[10];
    const float* dist_b  = (const float*)d_in[11];
    const float* scalar  = (const float*)d_in[12];
    const float* AWq     = (const float*)d_in[13];
    const float* Abq     = (const float*)d_in[14];
    const float* AWk     = (const float*)d_in[15];
    const float* Abk     = (const float*)d_in[16];
    const float* Wd      = (const float*)d_in[17];
    const float* bd      = (const float*)d_in[18];
    const float* g1      = (const float*)d_in[19];
    const float* beta1   = (const float*)d_in[20];
    const float* W1      = (const float*)d_in[21];
    const float* b1      = (const float*)d_in[22];
    const float* W2      = (const float*)d_in[23];
    const float* b2      = (const float*)d_in[24];
    const float* g2      = (const float*)d_in[25];
    const float* beta2   = (const float*)d_in[26];
    float* out = (float*)d_out;

    float *P, *ctx, *hbuf, *ffb, *part, *wf, *bf;
    cudaGetSymbolAddress((void**)&P,    g_P);
    cudaGetSymbolAddress((void**)&ctx,  g_ctx);
    cudaGetSymbolAddress((void**)&hbuf, g_h);
    cudaGetSymbolAddress((void**)&ffb,  g_ff);
    cudaGetSymbolAddress((void**)&part, g_part);
    cudaGetSymbolAddress((void**)&wf,   g_wf);
    cudaGetSymbolAddress((void**)&bf,   g_bf);

    // 1) fused attack weights + biases (plain launch; head of chain)
    fusew_kernel<<<dim3(8, 9), 128>>>(Wq, bq, Wk, bk, AWq, Abq, AWk, Abk, wf, bf);

    // 2) all 5 projections — PDL (segs 0-2 overlap fusew)
    {
        void* a[] = {&x, &Wq, &bq, &Wk, &bk, &Wv, &bv, &wf, &bf, &P};
        launch_pdl((const void*)proj_kernel, dim3(20, 32), dim3(128), a);
    }

    // 3) fused attention — PDL
    {
        void* a[] = {&P, &mask, &order_w, &order_b, &dist_w, &dist_b, &scalar, &ctx};
        launch_pdl((const void*)attn_kernel, dim3(SS / 16, NH, BB), dim3(256), a);
    }

    // 4) Wd split-K=8 (1024 blocks) — PDL
    {
        int N = HID, K = HID;
        void* a[] = {&ctx, &Wd, &part, &N, &K};
        launch_pdl((const void*)gemm_partial_t<8>, dim3(4, 32, 8), dim3(128), a);
    }

    // 5) LN1 — PDL
    {
        int dep = 0;
        void* a[] = {&part, &bd, &x, &g1, &beta1, &hbuf, &dep};
        launch_pdl((const void*)ln_kernel<8>, dim3(MM), dim3(256), a);
    }

    // 6) W1 + gelu — PDL
    {
        void* a[] = {&hbuf, &W1, &b1, &ffb};
        launch_pdl((const void*)gemm_w1, dim3(16, 32), dim3(128), a);
    }

    // 7) W2 split-K=8 — PDL
    {
        int N = HID, K = FF;
        void* a[] = {&ffb, &W2, &part, &N, &K};
        launch_pdl((const void*)gemm_partial_t<8>, dim3(4, 32, 8), dim3(128), a);
    }

    // 8) LN2 — PDL
    {
        int dep = 1;
        void* a[] = {&part, &b2, &hbuf, &g2, &beta2, &out, &dep};
        launch_pdl((const void*)ln_kernel<8>, dim3(MM), dim3(256), a);
    }
}

// round 15
// speedup vs baseline: 1.1249x; 1.1044x over previous
#include <cuda_runtime.h>
#include <math.h>
#include <stdint.h>

#define BB   8
#define SS   128
#define HID  256
#define NH   4
#define DH   64
#define FF   1024
#define MM   (BB*SS)        // 1024 rows
#define PSTR 1280           // proj buffer row stride: q|k|v|aq|ak

// ---------------- scratch ----------------------------------------------------
__device__ float g_P   [MM * PSTR];
__device__ float g_ctx [MM * HID];
__device__ float g_h   [MM * HID];
__device__ float g_ff  [MM * FF];
__device__ float g_part[8 * MM * HID];
__device__ float g_wf  [HID * 512];
__device__ float g_bf  [512];

// ---------------- helpers ------------------------------------------------------
__device__ __forceinline__ void cpa16(uint32_t smem, const void* gmem)
{
    asm volatile("cp.async.cg.shared.global [%0], [%1], 16;" :: "r"(smem), "l"(gmem));
}
#define CP_COMMIT() asm volatile("cp.async.commit_group;" ::: "memory")
#define CP_WAIT0()  asm volatile("cp.async.wait_group 0;" ::: "memory")

__device__ __forceinline__ void mma8(float* d,
                                     uint32_t a0, uint32_t a1, uint32_t a2, uint32_t a3,
                                     uint32_t b0, uint32_t b1)
{
    asm volatile(
        "mma.sync.aligned.m16n8k8.row.col.f32.tf32.tf32.f32 "
        "{%0,%1,%2,%3},{%4,%5,%6,%7},{%8,%9},{%0,%1,%2,%3};"
        : "+f"(d[0]), "+f"(d[1]), "+f"(d[2]), "+f"(d[3])
        : "r"(a0), "r"(a1), "r"(a2), "r"(a3), "r"(b0), "r"(b1));
}

// =============================================================================
// tf32 GEMM body (R11 winner): 128 threads (4 warps), block tile 32x64, BK=16,
// 2-stage cp.async double buffer. Raw fp32 bits fed to mma.tf32.
// =============================================================================
__device__ __forceinline__ void gemm_tf32(const float* __restrict__ A, int lda,
                                          const float* __restrict__ B, int ldb,
                                          int row0, int col0, int K,
                                          float acc[4][4])
{
    __shared__ uint32_t As[2][32][20];
    __shared__ uint32_t Bs[2][16][68];

    const int tid  = threadIdx.x;
    const int lane = tid & 31;
    const int w    = tid >> 5;
    const int g    = lane >> 2;
    const int tig  = lane & 3;
    const int rb   = (w & 1) << 4;
    const int cb   = (w >> 1) << 5;

    const int ar = tid >> 2, ac = (tid & 3) << 2;
    int br[2], bc[2];
#pragma unroll
    for (int u = 0; u < 2; u++) {
        int f = tid + 128 * u;
        br[u] = f >> 4;  bc[u] = (f & 15) << 2;
    }

    uint32_t sA[2], sB[2][2];
#pragma unroll
    for (int st = 0; st < 2; st++) {
        sA[st] = (uint32_t)__cvta_generic_to_shared(&As[st][ar][ac]);
#pragma unroll
        for (int u = 0; u < 2; u++)
            sB[st][u] = (uint32_t)__cvta_generic_to_shared(&Bs[st][br[u]][bc[u]]);
    }

    const float* Ap = A + (size_t)(row0 + ar) * lda + ac;
    const float* Bp0 = B + (size_t)br[0] * ldb + col0 + bc[0];
    const float* Bp1 = B + (size_t)br[1] * ldb + col0 + bc[1];

#pragma unroll
    for (int t = 0; t < 4; t++)
#pragma unroll
        for (int j = 0; j < 4; j++) acc[t][j] = 0.f;

    cpa16(sA[0], Ap);
    cpa16(sB[0][0], Bp0);
    cpa16(sB[0][1], Bp1);
    CP_COMMIT();

    const int nt = K >> 4;
    for (int kt = 0; kt < nt; kt++) {
        const int st = kt & 1;
        CP_WAIT0();
        __syncthreads();

        if (kt + 1 < nt) {
            int k0 = (kt + 1) << 4;
            cpa16(sA[st ^ 1], Ap + k0);
            cpa16(sB[st ^ 1][0], Bp0 + (size_t)k0 * ldb);
            cpa16(sB[st ^ 1][1], Bp1 + (size_t)k0 * ldb);
            CP_COMMIT();
        }

#pragma unroll
        for (int ks = 0; ks < 16; ks += 8) {
            uint32_t a0 = As[st][rb + g][ks + tig];
            uint32_t a1 = As[st][rb + g + 8][ks + tig];
            uint32_t a2 = As[st][rb + g][ks + tig + 4];
            uint32_t a3 = As[st][rb + g + 8][ks + tig + 4];
#pragma unroll
            for (int t = 0; t < 4; t++) {
                uint32_t b0 = Bs[st][ks + tig][cb + t * 8 + g];
                uint32_t b1 = Bs[st][ks + tig + 4][cb + t * 8 + g];
                mma8(acc[t], a0, a1, a2, a3, b0, b1);
            }
        }
    }
}

// =============================================================================
// fusew: wf = [Wq@AWq | Wk@AWk] (fp32 out), bf fused biases. grid (8,9).
// =============================================================================
__global__ __launch_bounds__(128)
void fusew_kernel(const float* __restrict__ Wq, const float* __restrict__ bq,
                  const float* __restrict__ Wk, const float* __restrict__ bk,
                  const float* __restrict__ AWq, const float* __restrict__ Abq,
                  const float* __restrict__ AWk, const float* __restrict__ Abk,
                  float* __restrict__ wf, float* __restrict__ bf)
{
    const int seg = blockIdx.x >> 2;
    const int wcol0 = (blockIdx.x & 3) * 64;

    if (blockIdx.y == 8) {
        const float* bin = seg ? bk : bq;
        const float* AW  = seg ? AWk : AWq;
        const float* Ab  = seg ? Abk : Abq;
        __shared__ float red[128];
        int t = threadIdx.x;
        int c = t & 63, half = t >> 6;
        float s = 0.f;
        for (int d = half * 128; d < half * 128 + 128; d++)
            s += bin[d] * AW[(size_t)d * HID + wcol0 + c];
        red[t] = s;
        __syncthreads();
        if (half == 0)
            bf[seg * 256 + wcol0 + c] = red[c] + red[64 + c] + Ab[wcol0 + c];
        return;
    }

    const float* A = seg ? Wk : Wq;
    const float* B = seg ? AWk : AWq;
    const int row0 = blockIdx.y * 32;
    float acc[4][4];
    gemm_tf32(A, HID, B, HID, row0, wcol0, HID, acc);

    const int lane = threadIdx.x & 31, w = threadIdx.x >> 5;
    const int g = lane >> 2, tig = lane & 3;
    const int rb = (w & 1) << 4, cb = (w >> 1) << 5;
#pragma unroll
    for (int t = 0; t < 4; t++) {
        int c = seg * 256 + wcol0 + cb + t * 8 + tig * 2;
        int r = row0 + rb + g;
        *(float2*)&wf[(size_t)r * 512 + c]       = make_float2(acc[t][0], acc[t][1]);
        *(float2*)&wf[(size_t)(r + 8) * 512 + c] = make_float2(acc[t][2], acc[t][3]);
    }
}

// =============================================================================
// proj: all 5 projections from x. grid (20,32), 128 threads.
// =============================================================================
__global__ __launch_bounds__(128)
void proj_kernel(const float* __restrict__ x,
                 const float* __restrict__ Wq, const float* __restrict__ bq,
                 const float* __restrict__ Wk, const float* __restrict__ bk,
                 const float* __restrict__ Wv, const float* __restrict__ bv,
                 const float* __restrict__ wf, const float* __restrict__ bf,
                 float* __restrict__ P)
{
    const int seg = blockIdx.x >> 2;
    const int wcol0 = (blockIdx.x & 3) * 64;
    const int row0 = blockIdx.y * 32;

    const float* W; const float* bias; int ldb; int bcol;
    if      (seg == 0) { W = Wq; bias = bq;        ldb = HID; bcol = wcol0; }
    else if (seg == 1) { W = Wk; bias = bk;        ldb = HID; bcol = wcol0; }
    else if (seg == 2) { W = Wv; bias = bv;        ldb = HID; bcol = wcol0; }
    else if (seg == 3) { W = wf; bias = bf;        ldb = 512; bcol = wcol0; }
    else               { W = wf; bias = bf + 256;  ldb = 512; bcol = 256 + wcol0; }

    if (seg >= 3) cudaGridDependencySynchronize();

    float acc[4][4];
    gemm_tf32(x, HID, W, ldb, row0, bcol, HID, acc);

    const int lane = threadIdx.x & 31, w = threadIdx.x >> 5;
    const int g = lane >> 2, tig = lane & 3;
    const int rb = (w & 1) << 4, cb = (w >> 1) << 5;
    const int ocol0 = blockIdx.x * 64;
#pragma unroll
    for (int t = 0; t < 4; t++) {
        int c = cb + t * 8 + tig * 2;
        int r = row0 + rb + g;
        float b0 = bias[wcol0 + c], b1 = bias[wcol0 + c + 1];
        *(float2*)&P[(size_t)r * PSTR + ocol0 + c] =
            make_float2(acc[t][0] + b0, acc[t][1] + b1);
        *(float2*)&P[(size_t)(r + 8) * PSTR + ocol0 + c] =
            make_float2(acc[t][2] + b0, acc[t][3] + b1);
    }
}

// =============================================================================
// Split-K partial GEMM. grid (N/64, M/32, NS).
// =============================================================================
template<int NS>
__global__ __launch_bounds__(128)
void gemm_partial_t(const float* __restrict__ A, const float* __restrict__ B,
                    float* __restrict__ Cp, int N, int K)
{
    const int ks = blockIdx.z;
    const int Ks = K / NS;
    const int row0 = blockIdx.y * 32;
    const int col0 = blockIdx.x * 64;

    cudaGridDependencySynchronize();

    float acc[4][4];
    gemm_tf32(A + (size_t)ks * Ks, K, B + (size_t)ks * Ks * N, N, row0, col0, Ks, acc);

    float* C = Cp + (size_t)ks * MM * N;
    const int lane = threadIdx.x & 31, w = threadIdx.x >> 5;
    const int g = lane >> 2, tig = lane & 3;
    const int rb = (w & 1) << 4, cb = (w >> 1) << 5;
#pragma unroll
    for (int t = 0; t < 4; t++) {
        int c = col0 + cb + t * 8 + tig * 2;
        int r = row0 + rb + g;
        *(float2*)&C[(size_t)r * N + c]       = make_float2(acc[t][0], acc[t][1]);
        *(float2*)&C[(size_t)(r + 8) * N + c] = make_float2(acc[t][2], acc[t][3]);
    }
}

// =============================================================================
// W1: h @ W1 + b1, gelu, fp32 out. grid (16,32).
// =============================================================================
__global__ __launch_bounds__(128)
void gemm_w1(const float* __restrict__ A, const float* __restrict__ B,
             const float* __restrict__ bias, float* __restrict__ C)
{
    const int row0 = blockIdx.y * 32;
    const int col0 = blockIdx.x * 64;

    cudaGridDependencySynchronize();

    float acc[4][4];
    gemm_tf32(A, HID, B, FF, row0, col0, HID, acc);

    const int lane = threadIdx.x & 31, w = threadIdx.x >> 5;
    const int g = lane >> 2, tig = lane & 3;
    const int rb = (w & 1) << 4, cb = (w >> 1) << 5;
    const float cg = 0.70710678118654752f;
#pragma unroll
    for (int t = 0; t < 4; t++) {
        int c = col0 + cb + t * 8 + tig * 2;
        int r = row0 + rb + g;
        float b0 = bias[c], b1 = bias[c + 1];
        float v00 = acc[t][0] + b0, v01 = acc[t][1] + b1;
        float v10 = acc[t][2] + b0, v11 = acc[t][3] + b1;
        v00 = 0.5f * v00 * (1.0f + erff(v00 * cg));
        v01 = 0.5f * v01 * (1.0f + erff(v01 * cg));
        v10 = 0.5f * v10 * (1.0f + erff(v10 * cg));
        v11 = 0.5f * v11 * (1.0f + erff(v11 * cg));
        *(float2*)&C[(size_t)r * FF + c]       = make_float2(v00, v01);
        *(float2*)&C[(size_t)(r + 8) * FF + c] = make_float2(v10, v11);
    }
}

// =============================================================================
// Fused attention with tensor-core score/ctx matmuls.
// 256 threads, 8 warps, block = 16 queries of one (b,h), grid 256 blocks.
// Dynamic smem layout (floats):
//   tile [128][68]  (k -> ak -> v)
//   qsh  [16][68]   (q -> aq)           [padded stride 68: conflict-free A frags]
//   sbuf [16][132]  (scores -> probs)
//   abuf [16][132]  (attack scores)
//   kokd [128][2], wsh [256]
// =============================================================================
#define AT_TILE 0
#define AT_QSH  (128*68)
#define AT_SBUF (AT_QSH + 16*68)
#define AT_ABUF (AT_SBUF + 16*132)
#define AT_KOKD (AT_ABUF + 16*132)
#define AT_WSH  (AT_KOKD + 256)
#define AT_BYTES ((AT_WSH + 256) * 4)

__device__ __forceinline__ void softmax4(const float x[4], float p[4])
{
    float m = fmaxf(fmaxf(x[0], x[1]), fmaxf(x[2], x[3]));
#pragma unroll
    for (int o = 16; o; o >>= 1) m = fmaxf(m, __shfl_xor_sync(0xffffffffu, m, o));
    float e0 = __expf(x[0] - m), e1 = __expf(x[1] - m);
    float e2 = __expf(x[2] - m), e3 = __expf(x[3] - m);
    float s = e0 + e1 + e2 + e3;
#pragma unroll
    for (int o = 16; o; o >>= 1) s += __shfl_xor_sync(0xffffffffu, s, o);
    float r = __fdividef(1.f, s);
    p[0] = e0 * r; p[1] = e1 * r; p[2] = e2 * r; p[3] = e3 * r;
}

__device__ __forceinline__ void softmax_chain(const float s[4], const float as[4],
                                              const float erro[4], const float errd[4],
                                              const float mk[4], float* prow, int lane)
{
    const float inv = 0.125f;
    float rich[4], orig[4], att[4];
#pragma unroll
    for (int jj = 0; jj < 4; jj++) {
        rich[jj] = (s[jj] + erro[jj] + errd[jj]) * inv + mk[jj];
        orig[jj] = s[jj] * inv + mk[jj];
        att[jj]  = as[jj] * inv + mk[jj];
    }
    float rich_p[4], orig_p[4], att_p[4], comb[4], comb_p[4], fin[4], fin_p[4];
    softmax4(rich, rich_p);
    softmax4(orig, orig_p);
    softmax4(att, att_p);
#pragma unroll
    for (int jj = 0; jj < 4; jj++) comb[jj] = orig_p[jj] + 0.5f * rich_p[jj];
    softmax4(comb, comb_p);
#pragma unroll
    for (int jj = 0; jj < 4; jj++) fin[jj] = comb_p[jj] + 0.5f * att_p[jj];
    softmax4(fin, fin_p);
#pragma unroll
    for (int jj = 0; jj < 4; jj++) prow[lane + 32 * jj] = fin_p[jj];
}

// warp-level [16 x 16] score tile via mma: keys [16w,16w+16), all 16 queries.
__device__ __forceinline__ void score_mma(const float* qsh, const float* tile,
                                          float* buf, int w, int g, int tig)
{
    float acc0[4] = {0, 0, 0, 0}, acc1[4] = {0, 0, 0, 0};
    const int j0 = 16 * w + g, j1 = j0 + 8;
#pragma unroll
    for (int ks = 0; ks < 64; ks += 8) {
        uint32_t a0 = __float_as_uint(qsh[g * 68 + ks + tig]);
        uint32_t a1 = __float_as_uint(qsh[(g + 8) * 68 + ks + tig]);
        uint32_t a2 = __float_as_uint(qsh[g * 68 + ks + tig + 4]);
        uint32_t a3 = __float_as_uint(qsh[(g + 8) * 68 + ks + tig + 4]);
        uint32_t b00 = __float_as_uint(tile[j0 * 68 + ks + tig]);
        uint32_t b01 = __float_as_uint(tile[j0 * 68 + ks + tig + 4]);
        uint32_t b10 = __float_as_uint(tile[j1 * 68 + ks + tig]);
        uint32_t b11 = __float_as_uint(tile[j1 * 68 + ks + tig + 4]);
        mma8(acc0, a0, a1, a2, a3, b00, b01);
        mma8(acc1, a0, a1, a2, a3, b10, b11);
    }
    int c0 = 16 * w + tig * 2;
    *(float2*)&buf[g * 132 + c0]           = make_float2(acc0[0], acc0[1]);
    *(float2*)&buf[(g + 8) * 132 + c0]     = make_float2(acc0[2], acc0[3]);
    *(float2*)&buf[g * 132 + c0 + 8]       = make_float2(acc1[0], acc1[1]);
    *(float2*)&buf[(g + 8) * 132 + c0 + 8] = make_float2(acc1[2], acc1[3]);
}

__global__ __launch_bounds__(256)
void attn_kernel(const float* __restrict__ P, const float* __restrict__ mask,
                 const float* __restrict__ order_w, const float* __restrict__ order_b,
                 const float* __restrict__ dist_w, const float* __restrict__ dist_b,
                 const float* __restrict__ scalar, float* __restrict__ ctx)
{
    extern __shared__ float sm[];
    float* tile = sm + AT_TILE;   // [128][68]
    float* qsh  = sm + AT_QSH;    // [16][68]
    float* sbuf = sm + AT_SBUF;   // [16][132]
    float* abuf = sm + AT_ABUF;   // [16][132]
    float* kokd = sm + AT_KOKD;   // [128][2]
    float* wsh  = sm + AT_WSH;    // [256]

    const int tid = threadIdx.x;
    const int lane = tid & 31;
    const int w = tid >> 5;
    const int g = lane >> 2;
    const int tig = lane & 3;
    const int h = blockIdx.y, b = blockIdx.z;
    const int i0 = blockIdx.x * 16;
    const int ia = i0 + w;
    const int ib = i0 + w + 8;

    const size_t rowbase = ((size_t)b * SS) * PSTR + h * DH;

    // prefetch mask rows + small params before PDL sync
    float mkA[4], mkB[4];
#pragma unroll
    for (int jj = 0; jj < 4; jj++) {
        int j = lane + 32 * jj;
        mkA[jj] = mask[((size_t)b * SS + ia) * SS + j];
        mkB[jj] = mask[((size_t)b * SS + ib) * SS + j];
    }
    const float ob = order_b[0], db = dist_b[0], sc = scalar[0];
    wsh[tid] = (tid < 128) ? order_w[tid] : dist_w[tid - 128];

    cudaGridDependencySynchronize();

    // ---- phase 1: k tile + q rows
#pragma unroll
    for (int f = tid; f < 128 * 16; f += 256) {
        int j = f >> 4, d4 = (f & 15) << 2;
        *(float4*)&tile[j * 68 + d4] = *(const float4*)&P[rowbase + (size_t)j * PSTR + 256 + d4];
    }
    {
        int r = tid >> 4, d4 = (tid & 15) << 2;
        *(float4*)&qsh[r * 68 + d4] = *(const float4*)&P[rowbase + (size_t)(i0 + r) * PSTR + d4];
    }
    __syncthreads();

    // scores via mma -> sbuf
    score_mma(qsh, tile, sbuf, w, g, tig);

    // per-key order/dist projections
    if (tid < 128) {
        float ko = 0, kd = 0;
#pragma unroll
        for (int d4 = 0; d4 < 64; d4 += 4) {
            float4 kv = *(const float4*)&tile[tid * 68 + d4];
            float4 ov = *(const float4*)&wsh[64 + d4];
            float4 dv = *(const float4*)&wsh[192 + d4];
            ko = fmaf(kv.x, ov.x, fmaf(kv.y, ov.y, fmaf(kv.z, ov.z, fmaf(kv.w, ov.w, ko))));
            kd = fmaf(kv.x, dv.x, fmaf(kv.y, dv.y, fmaf(kv.z, dv.z, fmaf(kv.w, dv.w, kd))));
        }
        kokd[tid * 2 + 0] = ko; kokd[tid * 2 + 1] = kd;
    }
    // per-query order/dist projections
    float qoA = qsh[w * 68 + lane] * wsh[lane] + qsh[w * 68 + lane + 32] * wsh[32 + lane];
    float qdA = qsh[w * 68 + lane] * wsh[128 + lane] + qsh[w * 68 + lane + 32] * wsh[160 + lane];
    float qoB = qsh[(w + 8) * 68 + lane] * wsh[lane] + qsh[(w + 8) * 68 + lane + 32] * wsh[32 + lane];
    float qdB = qsh[(w + 8) * 68 + lane] * wsh[128 + lane] + qsh[(w + 8) * 68 + lane + 32] * wsh[160 + lane];
#pragma unroll
    for (int o = 16; o; o >>= 1) {
        qoA += __shfl_xor_sync(0xffffffffu, qoA, o);
        qdA += __shfl_xor_sync(0xffffffffu, qdA, o);
        qoB += __shfl_xor_sync(0xffffffffu, qoB, o);
        qdB += __shfl_xor_sync(0xffffffffu, qdB, o);
    }
    __syncthreads();

    // ---- phase 2: ak tile + aq rows; wsh becomes gdd table
#pragma unroll
    for (int f = tid; f < 128 * 16; f += 256) {
        int j = f >> 4, d4 = (f & 15) << 2;
        *(float4*)&tile[j * 68 + d4] = *(const float4*)&P[rowbase + (size_t)j * PSTR + 1024 + d4];
    }
    {
        int r = tid >> 4, d4 = (tid & 15) << 2;
        *(float4*)&qsh[r * 68 + d4] = *(const float4*)&P[rowbase + (size_t)(i0 + r) * PSTR + 768 + d4];
    }
    wsh[tid] = __logf(fabsf((float)(tid - 128)) + 1.0f);
    __syncthreads();

    // attack scores via mma -> abuf
    score_mma(qsh, tile, abuf, w, g, tig);
    __syncthreads();   // abuf complete; ak reads done -> tile free for v

    // issue v loads (overlap with softmax math)
    float4 vreg[8];
#pragma unroll
    for (int t = 0; t < 8; t++) {
        int f = tid + t * 256;
        int j = f >> 4, d4 = (f & 15) << 2;
        vreg[t] = *(const float4*)&P[rowbase + (size_t)j * PSTR + 512 + d4];
    }

    // ---- error terms + 5 softmaxes per query; probs overwrite sbuf rows
    const float sc2h = 0.5f * sc * sc;
    float sA[4], sB4[4], aA[4], aB[4], erro[4], errd[4];
#pragma unroll
    for (int jj = 0; jj < 4; jj++) {
        sA[jj]  = sbuf[w * 132 + lane + 32 * jj];
        sB4[jj] = sbuf[(w + 8) * 132 + lane + 32 * jj];
        aA[jj]  = abuf[w * 132 + lane + 32 * jj];
        aB[jj]  = abuf[(w + 8) * 132 + lane + 32 * jj];
    }

    // query A
#pragma unroll
    for (int jj = 0; jj < 4; jj++) {
        int j = lane + 32 * jj;
        float z = qoA + kokd[j * 2 + 0] + ob;
        float sp = fmaxf(z, 0.f) + __logf(1.f + __expf(-fabsf(z)));
        erro[jj] = ((j > ia) ? z : 0.f) - sp;
        float diff = wsh[j - ia + 128] - (qdA + kokd[j * 2 + 1] + db);
        errd[jj] = -diff * diff * sc2h;
    }
    softmax_chain(sA, aA, erro, errd, mkA, &sbuf[w * 132], lane);

    // query B
#pragma unroll
    for (int jj = 0; jj < 4; jj++) {
        int j = lane + 32 * jj;
        float z = qoB + kokd[j * 2 + 0] + ob;
        float sp = fmaxf(z, 0.f) + __logf(1.f + __expf(-fabsf(z)));
        erro[jj] = ((j > ib) ? z : 0.f) - sp;
        float diff = wsh[j - ib + 128] - (qdB + kokd[j * 2 + 1] + db);
        errd[jj] = -diff * diff * sc2h;
    }
    softmax_chain(sB4, aB, erro, errd, mkB, &sbuf[(w + 8) * 132], lane);

    // commit v tile
#pragma unroll
    for (int t = 0; t < 8; t++) {
        int f = tid + t * 256;
        int j = f >> 4, d4 = (f & 15) << 2;
        *(float4*)&tile[j * 68 + d4] = vreg[t];
    }
    __syncthreads();   // probs (sbuf) + v (tile) visible to all warps

    // ---- ctx via mma: probs[16,128] @ v[128,64]; warp w covers d-cols [8w,8w+8)
    {
        float acc[4] = {0, 0, 0, 0};
#pragma unroll
        for (int ks = 0; ks < 128; ks += 8) {
            uint32_t a0 = __float_as_uint(sbuf[g * 132 + ks + tig]);
            uint32_t a1 = __float_as_uint(sbuf[(g + 8) * 132 + ks + tig]);
            uint32_t a2 = __float_as_uint(sbuf[g * 132 + ks + tig + 4]);
            uint32_t a3 = __float_as_uint(sbuf[(g + 8) * 132 + ks + tig + 4]);
            uint32_t b0 = __float_as_uint(tile[(ks + tig) * 68 + w * 8 + g]);
            uint32_t b1 = __float_as_uint(tile[(ks + tig + 4) * 68 + w * 8 + g]);
            mma8(acc, a0, a1, a2, a3, b0, b1);
        }
        int col = w * 8 + tig * 2;
        size_t o0 = ((size_t)(b * SS + i0 + g)) * HID + h * DH + col;
        size_t o1 = ((size_t)(b * SS + i0 + g + 8)) * HID + h * DH + col;
        *(float2*)&ctx[o0] = make_float2(acc[0], acc[1]);
        *(float2*)&ctx[o1] = make_float2(acc[2], acc[3]);
    }
}

// =============================================================================
// LayerNorm over NP split-K partials + bias + residual.
// =============================================================================
template<int NP>
__global__ __launch_bounds__(256)
void ln_kernel(const float* __restrict__ Cp, const float* __restrict__ bias,
               const float* __restrict__ res, const float* __restrict__ g,
               const float* __restrict__ beta, float* __restrict__ out,
               int res_dep)
{
    int row = blockIdx.x;
    int t = threadIdx.x;
    int lane = t & 31, w = t >> 5;
    __shared__ float red[8];

    const size_t SZ = (size_t)MM * HID;
    size_t idx = (size_t)row * HID + t;

    float x;
    if (res_dep) {
        cudaGridDependencySynchronize();
        x = bias[t] + res[idx];
    } else {
        x = bias[t] + res[idx];
        cudaGridDependencySynchronize();
    }
#pragma unroll
    for (int p = 0; p < NP; p++) x += Cp[p * SZ + idx];

    float v = x;
#pragma unroll
    for (int o = 16; o; o >>= 1) v += __shfl_xor_sync(0xffffffffu, v, o);
    if (lane == 0) red[w] = v;
    __syncthreads();
    float mean;
    {
        float r = (lane < 8) ? red[lane] : 0.f;
#pragma unroll
        for (int o = 4; o; o >>= 1) r += __shfl_xor_sync(0xffffffffu, r, o);
        mean = __shfl_sync(0xffffffffu, r, 0) * (1.0f / HID);
    }
    float d = x - mean;
    v = d * d;
#pragma unroll
    for (int o = 16; o; o >>= 1) v += __shfl_xor_sync(0xffffffffu, v, o);
    __syncthreads();
    if (lane == 0) red[w] = v;
    __syncthreads();
    float var;
    {
        float r = (lane < 8) ? red[lane] : 0.f;
#pragma unroll
        for (int o = 4; o; o >>= 1) r += __shfl_xor_sync(0xffffffffu, r, o);
        var = __shfl_sync(0xffffffffu, r, 0) * (1.0f / HID);
    }
    float invs = rsqrtf(var + 1e-12f);
    out[idx] = d * invs * g[t] + beta[t];
}

// ---------------- PDL launcher -------------------------------------------------
static inline void launch_pdl(const void* func, dim3 grid, dim3 block, void** args,
                              size_t dsmem = 0)
{
    cudaLaunchConfig_t cfg = {};
    cfg.gridDim = grid;
    cfg.blockDim = block;
    cfg.dynamicSmemBytes = dsmem;
    cfg.stream = 0;
    cudaLaunchAttribute attr[1];
    attr[0].id = cudaLaunchAttributeProgrammaticStreamSerialization;
    attr[0].val.programmaticStreamSerializationAllowed = 1;
    cfg.attrs = attr;
    cfg.numAttrs = 1;
    cudaLaunchKernelExC(&cfg, func, args);
}

// ---------------- launch -----------------------------------------------------
extern "C" void kernel_launch(void* const* d_in, const int* in_sizes, int n_in,
                              void* d_out, int out_size)
{
    const float* x       = (const float*)d_in[0];
    const float* mask    = (const float*)d_in[1];
    const float* Wq      = (const float*)d_in[2];
    const float* bq      = (const float*)d_in[3];
    const float* Wk      = (const float*)d_in[4];
    const float* bk      = (const float*)d_in[5];
    const float* Wv      = (const float*)d_in[6];
    const float* bv      = (const float*)d_in[7];
    const float* order_w = (const float*)d_in[8];
    const float* order_b = (const float*)d_in[9];
    const float* dist_w  = (const float*)d_in[10];
    const float* dist_b  = (const float*)d_in[11];
    const float* scalar  = (const float*)d_in[12];
    const float* AWq     = (const float*)d_in[13];
    const float* Abq     = (const float*)d_in[14];
    const float* AWk     = (const float*)d_in[15];
    const float* Abk     = (const float*)d_in[16];
    const float* Wd      = (const float*)d_in[17];
    const float* bd      = (const float*)d_in[18];
    const float* g1      = (const float*)d_in[19];
    const float* beta1   = (const float*)d_in[20];
    const float* W1      = (const float*)d_in[21];
    const float* b1      = (const float*)d_in[22];
    const float* W2      = (const float*)d_in[23];
    const float* b2      = (const float*)d_in[24];
    const float* g2      = (const float*)d_in[25];
    const float* beta2   = (const float*)d_in[26];
    float* out = (float*)d_out;

    float *P, *ctx, *hbuf, *ffb, *part, *wf, *bf;
    cudaGetSymbolAddress((void**)&P,    g_P);
    cudaGetSymbolAddress((void**)&ctx,  g_ctx);
    cudaGetSymbolAddress((void**)&hbuf, g_h);
    cudaGetSymbolAddress((void**)&ffb,  g_ff);
    cudaGetSymbolAddress((void**)&part, g_part);
    cudaGetSymbolAddress((void**)&wf,   g_wf);
    cudaGetSymbolAddress((void**)&bf,   g_bf);

    // allow >48KB dynamic smem for attn (idempotent host call)
    cudaFuncSetAttribute((const void*)attn_kernel,
                         cudaFuncAttributeMaxDynamicSharedMemorySize, AT_BYTES);

    // 1) fused attack weights + biases (plain launch; head of chain)
    fusew_kernel<<<dim3(8, 9), 128>>>(Wq, bq, Wk, bk, AWq, Abq, AWk, Abk, wf, bf);

    // 2) all 5 projections — PDL (segs 0-2 overlap fusew)
    {
        void* a[] = {&x, &Wq, &bq, &Wk, &bk, &Wv, &bv, &wf, &bf, &P};
        launch_pdl((const void*)proj_kernel, dim3(20, 32), dim3(128), a);
    }

    // 3) fused attention — PDL, dynamic smem
    {
        void* a[] = {&P, &mask, &order_w, &order_b, &dist_w, &dist_b, &scalar, &ctx};
        launch_pdl((const void*)attn_kernel, dim3(SS / 16, NH, BB), dim3(256), a,
                   AT_BYTES);
    }

    // 4) Wd split-K=8 (1024 blocks) — PDL
    {
        int N = HID, K = HID;
        void* a[] = {&ctx, &Wd, &part, &N, &K};
        launch_pdl((const void*)gemm_partial_t<8>, dim3(4, 32, 8), dim3(128), a);
    }

    // 5) LN1 — PDL
    {
        int dep = 0;
        void* a[] = {&part, &bd, &x, &g1, &beta1, &hbuf, &dep};
        launch_pdl((const void*)ln_kernel<8>, dim3(MM), dim3(256), a);
    }

    // 6) W1 + gelu — PDL
    {
        void* a[] = {&hbuf, &W1, &b1, &ffb};
        launch_pdl((const void*)gemm_w1, dim3(16, 32), dim3(128), a);
    }

    // 7) W2 split-K=8 — PDL
    {
        int N = HID, K = FF;
        void* a[] = {&ffb, &W2, &part, &N, &K};
        launch_pdl((const void*)gemm_partial_t<8>, dim3(4, 32, 8), dim3(128), a);
    }

    // 8) LN2 — PDL
    {
        int dep = 1;
        void* a[] = {&part, &b2, &hbuf, &g2, &beta2, &out, &dep};
        launch_pdl((const void*)ln_kernel<8>, dim3(MM), dim3(256), a);
    }
}